// round 16
// baseline (speedup 1.0000x reference)
#include <cuda_runtime.h>
#include <math.h>
#include <stdint.h>

// ---------------- problem constants ----------------
#define BATCH   32
#define SEQ     5000
#define DIMM    256
#define HEADS   8
#define DHEAD   32
#define INNERD  256
#define MLPD    1024
#define NLAYER  4
#define NTOK    160000
#define ATT_SCALE 0.17677669529663688f   // 32^-0.5
#define WSLICE  10                        // k_wsum sequence slices (5000 = 10*500)

// ---------------- static device scratch ----------------
__device__ float g_xn[(size_t)NTOK * DIMM];        // LN(x) -> FFN input (164 MB)
__device__ float g_hid[(size_t)NTOK * MLPD];       // FFN hidden (655 MB)
__device__ float g_dots[BATCH * HEADS * SEQ];
__device__ float g_u[BATCH * HEADS * DIMM];
__device__ float g_w[BATCH * HEADS * DIMM];
__device__ float g_ms[BATCH * HEADS * 2];
__device__ int   g_idx[BATCH];

// ================= PTX helpers (plain sm_103-safe) =================
__device__ __forceinline__ uint32_t smem_u32(const void* p) {
    uint32_t a;
    asm("{ .reg .u64 t; cvta.to.shared.u64 t, %1; cvt.u32.u64 %0, t; }"
        : "=r"(a) : "l"(p));
    return a;
}
__device__ __forceinline__ uint32_t f2tf32(float f) {
    uint32_t r;
    asm("cvt.rna.tf32.f32 %0, %1;" : "=r"(r) : "f"(f));
    return r;
}
__device__ __forceinline__ void mma_tf32(float* c, const uint32_t* a, const uint32_t* b) {
    asm volatile(
        "mma.sync.aligned.m16n8k8.row.col.f32.tf32.tf32.f32 "
        "{%0,%1,%2,%3}, {%4,%5,%6,%7}, {%8,%9}, {%0,%1,%2,%3};"
        : "+f"(c[0]), "+f"(c[1]), "+f"(c[2]), "+f"(c[3])
        : "r"(a[0]), "r"(a[1]), "r"(a[2]), "r"(a[3]), "r"(b[0]), "r"(b[1]));
}
#define CP_ASYNC16(dst, src) \
    asm volatile("cp.async.cg.shared.global [%0], [%1], 16;" :: "r"(dst), "l"(src))
#define CP_COMMIT  asm volatile("cp.async.commit_group;" ::: "memory")
#define CP_WAIT1   asm volatile("cp.async.wait_group 1;" ::: "memory")
#define CP_WAIT0   asm volatile("cp.async.wait_group 0;" ::: "memory")

// ================= attention / small kernels =================

__global__ void k_idx(const int* __restrict__ pidx, const int* __restrict__ hp_ptr)
{
    int t = threadIdx.x;
    int hp = 100;
    if (hp_ptr) { int v = *hp_ptr; if (v > 0 && v <= 100000) hp = v; }
    if (t < BATCH) g_idx[t] = pidx[2 * t] * hp + pidx[2 * t + 1];
}

__global__ void k_qu(const float* __restrict__ x,
                     const float* __restrict__ Wq,
                     const float* __restrict__ Wk)
{
    __shared__ float sel[DIMM];
    __shared__ float qs[INNERD];
    int b = blockIdx.x, t = threadIdx.x;
    const float* xr = x + ((size_t)b * SEQ + g_idx[b]) * DIMM;
    sel[t] = xr[t];
    #pragma unroll
    for (int p = 0; p < 8; p++) g_w[b * HEADS * DIMM + p * 256 + t] = 0.f;
    __syncthreads();

    float acc = 0.f;
    #pragma unroll 4
    for (int c = 0; c < DIMM; c++) acc += sel[c] * Wq[c * INNERD + t];
    qs[t] = acc;
    __syncthreads();

    #pragma unroll
    for (int p = 0; p < 8; p++) {
        int lin = p * 256 + t;
        int h = lin >> 8, c = lin & 255;
        const float* wk = Wk + c * INNERD + h * DHEAD;
        float u = 0.f;
        #pragma unroll
        for (int d = 0; d < DHEAD; d++) u += qs[h * DHEAD + d] * wk[d];
        g_u[(b * HEADS + h) * DIMM + c] = u * ATT_SCALE;
    }
}

__global__ void k_dots(const float* __restrict__ x)
{
    __shared__ float us[HEADS * DIMM];
    __shared__ float xs[32 * 257];
    int b = blockIdx.y, tile = blockIdx.x, t = threadIdx.x;
    int n0 = tile * 32;

    for (int i = t; i < HEADS * DIMM; i += 256) us[i] = g_u[b * HEADS * DIMM + i];
    for (int i = t; i < 32 * DIMM; i += 256) {
        int r = i >> 8, c = i & 255;
        int n = n0 + r;
        xs[r * 257 + c] = (n < SEQ) ? x[((size_t)b * SEQ + n) * DIMM + c] : 0.f;
    }
    __syncthreads();

    int tok = t & 31, h = t >> 5;
    float acc = 0.f;
    #pragma unroll 8
    for (int c = 0; c < DIMM; c++) acc += xs[tok * 257 + c] * us[h * DIMM + c];
    int n = n0 + tok;
    if (n < SEQ) g_dots[(size_t)(b * HEADS + h) * SEQ + n] = acc;
}

__global__ void k_stats()
{
    __shared__ float red[256];
    int bh = blockIdx.x, t = threadIdx.x;
    const float* d = g_dots + (size_t)bh * SEQ;

    float m = -1e30f;
    for (int n = t; n < SEQ; n += 256) m = fmaxf(m, d[n]);
    red[t] = m; __syncthreads();
    for (int s = 128; s > 0; s >>= 1) { if (t < s) red[t] = fmaxf(red[t], red[t + s]); __syncthreads(); }
    m = red[0]; __syncthreads();

    float sum = 0.f;
    for (int n = t; n < SEQ; n += 256) sum += expf(d[n] - m);
    red[t] = sum; __syncthreads();
    for (int s = 128; s > 0; s >>= 1) { if (t < s) red[t] += red[t + s]; __syncthreads(); }
    if (t == 0) { g_ms[2 * bh] = m; g_ms[2 * bh + 1] = 1.0f / red[0]; }
}

// sliced over sequence: grid (BATCH, WSLICE); atomicAdd partials into g_w
__global__ void k_wsum(const float* __restrict__ x)
{
    __shared__ float ps[256];
    __shared__ float mh[HEADS], ih[HEADS];
    int b = blockIdx.x, s = blockIdx.y, t = threadIdx.x;
    int n_start = s * (SEQ / WSLICE);
    int n_end = n_start + (SEQ / WSLICE);
    if (t < HEADS) { mh[t] = g_ms[2 * (b * HEADS + t)]; ih[t] = g_ms[2 * (b * HEADS + t) + 1]; }
    __syncthreads();

    float acc[HEADS];
    #pragma unroll
    for (int h = 0; h < HEADS; h++) acc[h] = 0.f;

    for (int n0 = n_start; n0 < n_end; n0 += 32) {
        int nn = n0 + (t >> 3), h = t & 7;
        ps[t] = (nn < n_end)
              ? expf(g_dots[(size_t)(b * HEADS + h) * SEQ + nn] - mh[h]) * ih[h]
              : 0.f;
        __syncthreads();
        int kmax = min(32, n_end - n0);
        for (int k = 0; k < kmax; k++) {
            float xv = x[((size_t)b * SEQ + n0 + k) * DIMM + t];
            #pragma unroll
            for (int h2 = 0; h2 < HEADS; h2++) acc[h2] += ps[k * 8 + h2] * xv;
        }
        __syncthreads();
    }
    #pragma unroll
    for (int h = 0; h < HEADS; h++)
        atomicAdd(&g_w[(b * HEADS + h) * DIMM + t], acc[h]);
}

__global__ void k_out(float* __restrict__ x,
                      const float* __restrict__ Wv,
                      const float* __restrict__ Wo,
                      const float* __restrict__ bo)
{
    __shared__ float ws[HEADS * DIMM];
    __shared__ float ts[INNERD];
    int b = blockIdx.x, t = threadIdx.x;
    for (int i = t; i < HEADS * DIMM; i += 256) ws[i] = g_w[b * HEADS * DIMM + i];
    __syncthreads();

    int h = t >> 5;
    float tv = 0.f;
    #pragma unroll 4
    for (int c = 0; c < DIMM; c++) tv += ws[h * DIMM + c] * Wv[c * INNERD + t];
    ts[t] = tv;
    __syncthreads();

    float acc = bo[t];
    #pragma unroll 4
    for (int j = 0; j < INNERD; j++) acc += ts[j] * Wo[j * DIMM + t];
    x[((size_t)b * SEQ + g_idx[b]) * DIMM + t] += acc;
}

// warp-per-token LayerNorm. grid = NTOK/8, block 256. dst==nullptr -> g_xn.
__global__ void k_ln(const float* __restrict__ xin, float* dst,
                     const float* __restrict__ gg, const float* __restrict__ bb)
{
    int w = threadIdx.x >> 5, lane = threadIdx.x & 31;
    size_t tok = (size_t)blockIdx.x * 8 + w;
    const float* xr = xin + tok * DIMM;
    float* out = (dst ? dst : g_xn) + tok * DIMM;

    float v[8], s = 0.f, s2 = 0.f;
    #pragma unroll
    for (int i = 0; i < 8; i++) {
        v[i] = xr[i * 32 + lane];
        s += v[i]; s2 += v[i] * v[i];
    }
    #pragma unroll
    for (int o = 16; o > 0; o >>= 1) {
        s  += __shfl_xor_sync(0xffffffffu, s, o);
        s2 += __shfl_xor_sync(0xffffffffu, s2, o);
    }
    float mean = s * (1.0f / DIMM);
    float rs = rsqrtf(s2 * (1.0f / DIMM) - mean * mean + 1e-5f);
    #pragma unroll
    for (int i = 0; i < 8; i++)
        out[i * 32 + lane] = (v[i] - mean) * rs * gg[i * 32 + lane] + bb[i * 32 + lane];
}

// ================= tf32 mma.sync FFN GEMM =================
// C[128,128] per CTA.  A row-major [M][K] (g_xn or g_hid), B = W row-major [K][N]
// (matches the .col B-fragment directly: b[k][n]).
// EPI==1: g_hid = gelu(C + bias)      (KDIM=256,  NN=1024)
// EPI==2: Cx   += C + bias            (KDIM=1024, NN=256)
//
// SMEM (dynamic, 71680 B):
//   As: 2 buffers of [128][36] floats  (stride 36 -> bank = 4*row+col, conflict-free)
//   Bs: 2 buffers of [32][136] floats  (stride 136 -> bank = 8*k+n,   conflict-free)
#define A_BUF_F  4608            // 128*36 floats per buffer
#define B_BUF_F  4352            // 32*136 floats per buffer
#define B_BASE_B 36864           // byte offset of Bs region
#define A_I_STRIDE_B 4608        // 32 rows * 36 floats * 4 B  (per-i dst stride, BYTES)
#define B_I_STRIDE_B 4352        // 8 rows * 136 floats * 4 B  (per-i dst stride, BYTES)
#define GSMEM_BYTES 71680

template<int KDIM, int NN, int EPI>
__global__ void __launch_bounds__(256, 2)
k_mma_gemm(const float* __restrict__ W, const float* __restrict__ bias,
           float* __restrict__ Cx)
{
    extern __shared__ char smem[];
    float* Asf = (float*)smem;
    float* Bsf = (float*)(smem + B_BASE_B);

    const float* A = (EPI == 1) ? g_xn : g_hid;
    const int m0 = blockIdx.x * 128;
    const int n0 = blockIdx.y * 128;
    const int tid = threadIdx.x;
    const int wid = tid >> 5, lane = tid & 31;
    const int wm = wid & 1, wn = wid >> 1;       // 2 x 4 warp grid
    const int g = lane >> 2, tig = lane & 3;

    // ---- cp.async source/dest addressing ----
    const uint32_t sb = smem_u32(smem);
    const uint32_t a_dst0 = sb + (((tid >> 3) * 36 + (tid & 7) * 4) << 2);
    const uint32_t b_dst0 = sb + B_BASE_B + (((tid >> 5) * 136 + (tid & 31) * 4) << 2);
    const float* a_src0 = A + (size_t)(m0 + (tid >> 3)) * KDIM + (tid & 7) * 4;
    const float* b_src0 = W + (size_t)(tid >> 5) * NN + n0 + (tid & 31) * 4;

    float acc[4][4][4];
    #pragma unroll
    for (int mi = 0; mi < 4; mi++)
        #pragma unroll
        for (int ni = 0; ni < 4; ni++)
            #pragma unroll
            for (int r = 0; r < 4; r++) acc[mi][ni][r] = 0.f;

    const int NKT = KDIM / 32;

    // ---- prologue: stages 0 and 1 ----
    #pragma unroll
    for (int st = 0; st < 2; st++) {
        uint32_t ad = a_dst0 + st * (A_BUF_F * 4);
        uint32_t bd = b_dst0 + st * (B_BUF_F * 4);
        const float* as = a_src0 + st * 32;
        const float* bs = b_src0 + (size_t)st * 32 * NN;
        #pragma unroll
        for (int i = 0; i < 4; i++) {
            CP_ASYNC16(ad + i * A_I_STRIDE_B, as + (size_t)i * 32 * KDIM);
            CP_ASYNC16(bd + i * B_I_STRIDE_B, bs + (size_t)i * 8 * NN);
        }
        CP_COMMIT;
    }

    for (int kt = 0; kt < NKT; kt++) {
        int cur = kt & 1;
        if (kt == NKT - 1) { CP_WAIT0; } else { CP_WAIT1; }
        __syncthreads();

        const float* Ab = Asf + cur * A_BUF_F;
        const float* Bb = Bsf + cur * B_BUF_F;

        #pragma unroll
        for (int k0 = 0; k0 < 32; k0 += 8) {
            uint32_t af[4][4], bf[4][2];
            #pragma unroll
            for (int mi = 0; mi < 4; mi++) {
                int ar = wm * 64 + mi * 16 + g;
                af[mi][0] = f2tf32(Ab[ar * 36 + k0 + tig]);
                af[mi][1] = f2tf32(Ab[(ar + 8) * 36 + k0 + tig]);
                af[mi][2] = f2tf32(Ab[ar * 36 + k0 + tig + 4]);
                af[mi][3] = f2tf32(Ab[(ar + 8) * 36 + k0 + tig + 4]);
            }
            #pragma unroll
            for (int ni = 0; ni < 4; ni++) {
                int bc = wn * 32 + ni * 8 + g;
                bf[ni][0] = f2tf32(Bb[(k0 + tig) * 136 + bc]);
                bf[ni][1] = f2tf32(Bb[(k0 + tig + 4) * 136 + bc]);
            }
            #pragma unroll
            for (int mi = 0; mi < 4; mi++)
                #pragma unroll
                for (int ni = 0; ni < 4; ni++)
                    mma_tf32(acc[mi][ni], af[mi], bf[ni]);
        }

        if (kt + 2 < NKT) {
            __syncthreads();                 // everyone done reading buffer `cur`
            uint32_t ad = a_dst0 + cur * (A_BUF_F * 4);
            uint32_t bd = b_dst0 + cur * (B_BUF_F * 4);
            const float* as = a_src0 + (kt + 2) * 32;
            const float* bs = b_src0 + (size_t)(kt + 2) * 32 * NN;
            #pragma unroll
            for (int i = 0; i < 4; i++) {
                CP_ASYNC16(ad + i * A_I_STRIDE_B, as + (size_t)i * 32 * KDIM);
                CP_ASYNC16(bd + i * B_I_STRIDE_B, bs + (size_t)i * 8 * NN);
            }
            CP_COMMIT;
        }
    }

    // ---- epilogue ----
    #pragma unroll
    for (int mi = 0; mi < 4; mi++) {
        int row = m0 + wm * 64 + mi * 16 + g;
        #pragma unroll
        for (int ni = 0; ni < 4; ni++) {
            int col = n0 + wn * 32 + ni * 8 + 2 * tig;
            float bs0 = bias[col], bs1 = bias[col + 1];
            float v0 = acc[mi][ni][0] + bs0, v1 = acc[mi][ni][1] + bs1;
            float v2 = acc[mi][ni][2] + bs0, v3 = acc[mi][ni][3] + bs1;
            if (EPI == 1) {
                v0 = 0.5f * v0 * (1.0f + erff(v0 * 0.70710678118654752f));
                v1 = 0.5f * v1 * (1.0f + erff(v1 * 0.70710678118654752f));
                v2 = 0.5f * v2 * (1.0f + erff(v2 * 0.70710678118654752f));
                v3 = 0.5f * v3 * (1.0f + erff(v3 * 0.70710678118654752f));
                *(float2*)(g_hid + (size_t)row * NN + col)       = make_float2(v0, v1);
                *(float2*)(g_hid + (size_t)(row + 8) * NN + col) = make_float2(v2, v3);
            } else {
                float2 o0 = *(float2*)(Cx + (size_t)row * NN + col);
                float2 o1 = *(float2*)(Cx + (size_t)(row + 8) * NN + col);
                o0.x += v0; o0.y += v1; o1.x += v2; o1.y += v3;
                *(float2*)(Cx + (size_t)row * NN + col)       = o0;
                *(float2*)(Cx + (size_t)(row + 8) * NN + col) = o1;
            }
        }
    }
}

// ================= launch =================
extern "C" void kernel_launch(void* const* d_in, const int* in_sizes, int n_in,
                              void* d_out, int out_size)
{
    const float* x_in = (const float*)d_in[0];
    const int*   pidx = (const int*)  d_in[1];
    const float* Wq   = (const float*)d_in[2];
    const float* Wk   = (const float*)d_in[3];
    const float* Wv   = (const float*)d_in[4];
    const float* Wo   = (const float*)d_in[5];
    const float* bo   = (const float*)d_in[6];
    const float* lng  = (const float*)d_in[7];
    const float* lnb  = (const float*)d_in[8];
    const float* W1   = (const float*)d_in[9];
    const float* b1   = (const float*)d_in[10];
    const float* W2   = (const float*)d_in[11];
    const float* b2   = (const float*)d_in[12];
    const float* ng   = (const float*)d_in[13];
    const float* nb   = (const float*)d_in[14];
    const int*   hp   = (n_in > 16) ? (const int*)d_in[16] : nullptr;

    float* x = (float*)d_out;

    cudaFuncSetAttribute(k_mma_gemm<DIMM, MLPD, 1>,
                         cudaFuncAttributeMaxDynamicSharedMemorySize, GSMEM_BYTES);
    cudaFuncSetAttribute(k_mma_gemm<MLPD, DIMM, 2>,
                         cudaFuncAttributeMaxDynamicSharedMemorySize, GSMEM_BYTES);

    cudaMemcpyAsync(x, x_in, (size_t)NTOK * DIMM * sizeof(float),
                    cudaMemcpyDeviceToDevice);
    k_idx<<<1, 32>>>(pidx, hp);

    for (int l = 0; l < NLAYER; l++) {
        const size_t wOff = (size_t)l * DIMM * INNERD;
        const size_t fOff = (size_t)l * DIMM * MLPD;

        // --- attention (folded: no full K/V projections) ---
        k_qu   <<<BATCH, 256>>>(x, Wq + wOff, Wk + wOff);
        k_dots <<<dim3((SEQ + 31) / 32, BATCH), 256>>>(x);
        k_stats<<<BATCH * HEADS, 256>>>();
        k_wsum <<<dim3(BATCH, WSLICE), 256>>>(x);
        k_out  <<<BATCH, 256>>>(x, Wv + wOff, Wo + wOff, bo + (size_t)l * DIMM);

        // --- pre-LN -> g_xn ---
        k_ln<<<NTOK / 8, 256>>>(x, nullptr, lng + (size_t)l * DIMM, lnb + (size_t)l * DIMM);

        // --- FFN on tf32 tensor cores (mma.sync) ---
        k_mma_gemm<DIMM, MLPD, 1><<<dim3(NTOK / 128, MLPD / 128), 256, GSMEM_BYTES>>>(
            W1 + fOff, b1 + (size_t)l * MLPD, nullptr);
        k_mma_gemm<MLPD, DIMM, 2><<<dim3(NTOK / 128, DIMM / 128), 256, GSMEM_BYTES>>>(
            W2 + fOff, b2 + (size_t)l * DIMM, x);
    }

    k_ln<<<NTOK / 8, 256>>>(x, x, ng, nb);
}

// round 17
// speedup vs baseline: 1.6061x; 1.6061x over previous
#include <cuda_runtime.h>
#include <cuda_bf16.h>
#include <math.h>
#include <stdint.h>

// ---------------- problem constants ----------------
#define BATCH   32
#define SEQ     5000
#define DIMM    256
#define HEADS   8
#define DHEAD   32
#define INNERD  256
#define MLPD    1024
#define NLAYER  4
#define NTOK    160000
#define ATT_SCALE 0.17677669529663688f   // 32^-0.5
#define WSLICE  10

// ---------------- static device scratch ----------------
__device__ __nv_bfloat16 g_xnb[(size_t)NTOK * DIMM];   // LN(x) in bf16 (82 MB)
__device__ __nv_bfloat16 g_hid[(size_t)NTOK * MLPD];   // FFN hidden bf16 (327 MB)
__device__ __nv_bfloat16 g_w1b[(size_t)NLAYER * DIMM * MLPD];  // W1 bf16
__device__ __nv_bfloat16 g_w2b[(size_t)NLAYER * MLPD * DIMM];  // W2 bf16
__device__ float g_dots[BATCH * HEADS * SEQ];
__device__ float g_u[BATCH * HEADS * DIMM];
__device__ float g_w[BATCH * HEADS * DIMM];
__device__ float g_ms[BATCH * HEADS * 2];
__device__ int   g_idx[BATCH];

// ================= PTX helpers (plain sm_103-safe) =================
__device__ __forceinline__ uint32_t smem_u32(const void* p) {
    uint32_t a;
    asm("{ .reg .u64 t; cvta.to.shared.u64 t, %1; cvt.u32.u64 %0, t; }"
        : "=r"(a) : "l"(p));
    return a;
}
__device__ __forceinline__ void mma_bf16(float* c, const uint32_t* a, const uint32_t* b) {
    asm volatile(
        "mma.sync.aligned.m16n8k16.row.col.f32.bf16.bf16.f32 "
        "{%0,%1,%2,%3}, {%4,%5,%6,%7}, {%8,%9}, {%0,%1,%2,%3};"
        : "+f"(c[0]), "+f"(c[1]), "+f"(c[2]), "+f"(c[3])
        : "r"(a[0]), "r"(a[1]), "r"(a[2]), "r"(a[3]), "r"(b[0]), "r"(b[1]));
}
#define LDMX4(r0, r1, r2, r3, addr) \
    asm volatile("ldmatrix.sync.aligned.m8n8.x4.shared.b16 {%0,%1,%2,%3}, [%4];" \
        : "=r"(r0), "=r"(r1), "=r"(r2), "=r"(r3) : "r"(addr))
#define LDMX4T(r0, r1, r2, r3, addr) \
    asm volatile("ldmatrix.sync.aligned.m8n8.x4.trans.shared.b16 {%0,%1,%2,%3}, [%4];" \
        : "=r"(r0), "=r"(r1), "=r"(r2), "=r"(r3) : "r"(addr))
#define CP_ASYNC16(dst, src) \
    asm volatile("cp.async.cg.shared.global [%0], [%1], 16;" :: "r"(dst), "l"(src))
#define CP_COMMIT  asm volatile("cp.async.commit_group;" ::: "memory")
#define CP_WAIT1   asm volatile("cp.async.wait_group 1;" ::: "memory")
#define CP_WAIT0   asm volatile("cp.async.wait_group 0;" ::: "memory")

// ================= attention / small kernels (fp32, unchanged) =================

__global__ void k_idx(const int* __restrict__ pidx, const int* __restrict__ hp_ptr)
{
    int t = threadIdx.x;
    int hp = 100;
    if (hp_ptr) { int v = *hp_ptr; if (v > 0 && v <= 100000) hp = v; }
    if (t < BATCH) g_idx[t] = pidx[2 * t] * hp + pidx[2 * t + 1];
}

__global__ void k_qu(const float* __restrict__ x,
                     const float* __restrict__ Wq,
                     const float* __restrict__ Wk)
{
    __shared__ float sel[DIMM];
    __shared__ float qs[INNERD];
    int b = blockIdx.x, t = threadIdx.x;
    const float* xr = x + ((size_t)b * SEQ + g_idx[b]) * DIMM;
    sel[t] = xr[t];
    #pragma unroll
    for (int p = 0; p < 8; p++) g_w[b * HEADS * DIMM + p * 256 + t] = 0.f;
    __syncthreads();

    float acc = 0.f;
    #pragma unroll 4
    for (int c = 0; c < DIMM; c++) acc += sel[c] * Wq[c * INNERD + t];
    qs[t] = acc;
    __syncthreads();

    #pragma unroll
    for (int p = 0; p < 8; p++) {
        int lin = p * 256 + t;
        int h = lin >> 8, c = lin & 255;
        const float* wk = Wk + c * INNERD + h * DHEAD;
        float u = 0.f;
        #pragma unroll
        for (int d = 0; d < DHEAD; d++) u += qs[h * DHEAD + d] * wk[d];
        g_u[(b * HEADS + h) * DIMM + c] = u * ATT_SCALE;
    }
}

__global__ void k_dots(const float* __restrict__ x)
{
    __shared__ float us[HEADS * DIMM];
    __shared__ float xs[32 * 257];
    int b = blockIdx.y, tile = blockIdx.x, t = threadIdx.x;
    int n0 = tile * 32;

    for (int i = t; i < HEADS * DIMM; i += 256) us[i] = g_u[b * HEADS * DIMM + i];
    for (int i = t; i < 32 * DIMM; i += 256) {
        int r = i >> 8, c = i & 255;
        int n = n0 + r;
        xs[r * 257 + c] = (n < SEQ) ? x[((size_t)b * SEQ + n) * DIMM + c] : 0.f;
    }
    __syncthreads();

    int tok = t & 31, h = t >> 5;
    float acc = 0.f;
    #pragma unroll 8
    for (int c = 0; c < DIMM; c++) acc += xs[tok * 257 + c] * us[h * DIMM + c];
    int n = n0 + tok;
    if (n < SEQ) g_dots[(size_t)(b * HEADS + h) * SEQ + n] = acc;
}

__global__ void k_stats()
{
    __shared__ float red[256];
    int bh = blockIdx.x, t = threadIdx.x;
    const float* d = g_dots + (size_t)bh * SEQ;

    float m = -1e30f;
    for (int n = t; n < SEQ; n += 256) m = fmaxf(m, d[n]);
    red[t] = m; __syncthreads();
    for (int s = 128; s > 0; s >>= 1) { if (t < s) red[t] = fmaxf(red[t], red[t + s]); __syncthreads(); }
    m = red[0]; __syncthreads();

    float sum = 0.f;
    for (int n = t; n < SEQ; n += 256) sum += expf(d[n] - m);
    red[t] = sum; __syncthreads();
    for (int s = 128; s > 0; s >>= 1) { if (t < s) red[t] += red[t + s]; __syncthreads(); }
    if (t == 0) { g_ms[2 * bh] = m; g_ms[2 * bh + 1] = 1.0f / red[0]; }
}

__global__ void k_wsum(const float* __restrict__ x)
{
    __shared__ float ps[256];
    __shared__ float mh[HEADS], ih[HEADS];
    int b = blockIdx.x, s = blockIdx.y, t = threadIdx.x;
    int n_start = s * (SEQ / WSLICE);
    int n_end = n_start + (SEQ / WSLICE);
    if (t < HEADS) { mh[t] = g_ms[2 * (b * HEADS + t)]; ih[t] = g_ms[2 * (b * HEADS + t) + 1]; }
    __syncthreads();

    float acc[HEADS];
    #pragma unroll
    for (int h = 0; h < HEADS; h++) acc[h] = 0.f;

    for (int n0 = n_start; n0 < n_end; n0 += 32) {
        int nn = n0 + (t >> 3), h = t & 7;
        ps[t] = (nn < n_end)
              ? expf(g_dots[(size_t)(b * HEADS + h) * SEQ + nn] - mh[h]) * ih[h]
              : 0.f;
        __syncthreads();
        int kmax = min(32, n_end - n0);
        for (int k = 0; k < kmax; k++) {
            float xv = x[((size_t)b * SEQ + n0 + k) * DIMM + t];
            #pragma unroll
            for (int h2 = 0; h2 < HEADS; h2++) acc[h2] += ps[k * 8 + h2] * xv;
        }
        __syncthreads();
    }
    #pragma unroll
    for (int h = 0; h < HEADS; h++)
        atomicAdd(&g_w[(b * HEADS + h) * DIMM + t], acc[h]);
}

__global__ void k_out(float* __restrict__ x,
                      const float* __restrict__ Wv,
                      const float* __restrict__ Wo,
                      const float* __restrict__ bo)
{
    __shared__ float ws[HEADS * DIMM];
    __shared__ float ts[INNERD];
    int b = blockIdx.x, t = threadIdx.x;
    for (int i = t; i < HEADS * DIMM; i += 256) ws[i] = g_w[b * HEADS * DIMM + i];
    __syncthreads();

    int h = t >> 5;
    float tv = 0.f;
    #pragma unroll 4
    for (int c = 0; c < DIMM; c++) tv += ws[h * DIMM + c] * Wv[c * INNERD + t];
    ts[t] = tv;
    __syncthreads();

    float acc = bo[t];
    #pragma unroll 4
    for (int j = 0; j < INNERD; j++) acc += ts[j] * Wo[j * DIMM + t];
    x[((size_t)b * SEQ + g_idx[b]) * DIMM + t] += acc;
}

// warp-per-token LayerNorm. dstf!=nullptr -> fp32 out; else bf16 -> g_xnb.
__global__ void k_ln(const float* __restrict__ xin, float* dstf,
                     const float* __restrict__ gg, const float* __restrict__ bb)
{
    int w = threadIdx.x >> 5, lane = threadIdx.x & 31;
    size_t tok = (size_t)blockIdx.x * 8 + w;
    const float* xr = xin + tok * DIMM;

    float v[8], s = 0.f, s2 = 0.f;
    #pragma unroll
    for (int i = 0; i < 8; i++) {
        v[i] = xr[i * 32 + lane];
        s += v[i]; s2 += v[i] * v[i];
    }
    #pragma unroll
    for (int o = 16; o > 0; o >>= 1) {
        s  += __shfl_xor_sync(0xffffffffu, s, o);
        s2 += __shfl_xor_sync(0xffffffffu, s2, o);
    }
    float mean = s * (1.0f / DIMM);
    float rs = rsqrtf(s2 * (1.0f / DIMM) - mean * mean + 1e-5f);
    if (dstf) {
        float* out = dstf + tok * DIMM;
        #pragma unroll
        for (int i = 0; i < 8; i++)
            out[i * 32 + lane] = (v[i] - mean) * rs * gg[i * 32 + lane] + bb[i * 32 + lane];
    } else {
        __nv_bfloat16* out = g_xnb + tok * DIMM;
        #pragma unroll
        for (int i = 0; i < 8; i++)
            out[i * 32 + lane] = __float2bfloat16(
                (v[i] - mean) * rs * gg[i * 32 + lane] + bb[i * 32 + lane]);
    }
}

// fp32 -> bf16 weight convert
__global__ void k_cvt(const float* __restrict__ W, __nv_bfloat16* __restrict__ o, int n)
{
    int i = blockIdx.x * 256 + threadIdx.x;
    if (i < n) o[i] = __float2bfloat16(W[i]);
}

// ================= bf16 mma.sync FFN GEMM (ldmatrix + 3-stage cp.async) =================
// C[128,128] per CTA.  A row-major bf16 [M][K] (g_xnb or g_hid), B bf16 [K][N].
// grid: (NN/128, M/128)  -- n fastest so A streams once.
// EPI==1: g_hid = bf16(gelu(C + bias))   (KDIM=256,  NN=1024)
// EPI==2: Cx   += C + bias               (KDIM=1024, NN=256)
//
// SMEM per stage: A 128 rows x 80 B (32 bf16 + pad)  = 10240 B
//                 B  32 rows x 272 B (128 bf16 + pad) = 8704 B
// 3 stages; padded strides are conflict-free for 16B ldmatrix row reads.
#define A_STRIDE_B 80
#define A_STAGE_B  10240
#define B_STRIDE_B 272
#define B_STAGE_B  8704
#define B_REGION_B 30720          // 3 * A_STAGE_B
#define GSMEM_BYTES 56832         // 30720 + 3 * 8704

template<int KDIM, int NN, int EPI>
__global__ void __launch_bounds__(256, 2)
k_bgemm(const __nv_bfloat16* __restrict__ Wb, const float* __restrict__ bias,
        float* __restrict__ Cx)
{
    extern __shared__ char smem[];
    const __nv_bfloat16* A = (EPI == 1) ? g_xnb : g_hid;

    const int n0 = blockIdx.x * 128;
    const int m0 = blockIdx.y * 128;
    const int tid = threadIdx.x;
    const int wid = tid >> 5, lane = tid & 31;
    const int wm = wid & 1, wn = wid >> 1;       // 2 x 4 warp grid (64m x 32n per warp)
    const int g = lane >> 2, tig = lane & 3;

    const uint32_t sb = smem_u32(smem);

    // cp.async per-thread tasks (2 A chunks + 2 B chunks per stage)
    const int acr0 = tid >> 2,          ack0 = tid & 3;          // A chunk 0: row, kchunk
    const int acr1 = (tid + 256) >> 2,  ack1 = tid & 3;          // A chunk 1
    const int bcr0 = tid >> 4,          bcn0 = tid & 15;         // B chunk 0
    const int bcr1 = (tid + 256) >> 4,  bcn1 = tid & 15;         // B chunk 1

    // ldmatrix lane base offsets (within stage)
    const uint32_t a_lm = (uint32_t)(wm * 64 + (lane & 15)) * A_STRIDE_B + (lane >> 4) * 16;
    const uint32_t b_lm = (uint32_t)(lane & 15) * B_STRIDE_B
                        + (uint32_t)(wn * 32 + (lane >> 4) * 8) * 2;

    float acc[4][4][4];
    #pragma unroll
    for (int mi = 0; mi < 4; mi++)
        #pragma unroll
        for (int ni = 0; ni < 4; ni++)
            #pragma unroll
            for (int r = 0; r < 4; r++) acc[mi][ni][r] = 0.f;

    const int NKT = KDIM / 32;

    auto load_stage = [&](int kt, int buf) {
        uint32_t ab = sb + buf * A_STAGE_B;
        uint32_t bb = sb + B_REGION_B + buf * B_STAGE_B;
        CP_ASYNC16(ab + acr0 * A_STRIDE_B + ack0 * 16,
                   A + (size_t)(m0 + acr0) * KDIM + kt * 32 + ack0 * 8);
        CP_ASYNC16(ab + acr1 * A_STRIDE_B + ack1 * 16,
                   A + (size_t)(m0 + acr1) * KDIM + kt * 32 + ack1 * 8);
        CP_ASYNC16(bb + bcr0 * B_STRIDE_B + bcn0 * 16,
                   Wb + (size_t)(kt * 32 + bcr0) * NN + n0 + bcn0 * 8);
        CP_ASYNC16(bb + bcr1 * B_STRIDE_B + bcn1 * 16,
                   Wb + (size_t)(kt * 32 + bcr1) * NN + n0 + bcn1 * 8);
        CP_COMMIT;
    };

    load_stage(0, 0);
    load_stage(1, 1);

    for (int kt = 0; kt < NKT; kt++) {
        if (kt == NKT - 1) { CP_WAIT0; } else { CP_WAIT1; }
        __syncthreads();
        if (kt + 2 < NKT) load_stage(kt + 2, (kt + 2) % 3);

        int buf = kt % 3;
        uint32_t aBase = sb + buf * A_STAGE_B + a_lm;
        uint32_t bBase = sb + B_REGION_B + buf * B_STAGE_B + b_lm;

        #pragma unroll
        for (int s = 0; s < 2; s++) {           // two k16 steps per BK=32 stage
            uint32_t af[4][4], bf[4][2];
            #pragma unroll
            for (int mi = 0; mi < 4; mi++)
                LDMX4(af[mi][0], af[mi][1], af[mi][2], af[mi][3],
                      aBase + mi * (16 * A_STRIDE_B) + s * 32);
            #pragma unroll
            for (int p = 0; p < 2; p++) {
                uint32_t r0, r1, r2, r3;
                LDMX4T(r0, r1, r2, r3, bBase + p * 32 + s * (16 * B_STRIDE_B));
                bf[2 * p][0] = r0; bf[2 * p][1] = r1;
                bf[2 * p + 1][0] = r2; bf[2 * p + 1][1] = r3;
            }
            #pragma unroll
            for (int mi = 0; mi < 4; mi++)
                #pragma unroll
                for (int ni = 0; ni < 4; ni++)
                    mma_bf16(acc[mi][ni], af[mi], bf[ni]);
        }
    }

    // ---- epilogue ----
    #pragma unroll
    for (int mi = 0; mi < 4; mi++) {
        int row = m0 + wm * 64 + mi * 16 + g;
        #pragma unroll
        for (int ni = 0; ni < 4; ni++) {
            int col = n0 + wn * 32 + ni * 8 + 2 * tig;
            float bs0 = bias[col], bs1 = bias[col + 1];
            float v0 = acc[mi][ni][0] + bs0, v1 = acc[mi][ni][1] + bs1;
            float v2 = acc[mi][ni][2] + bs0, v3 = acc[mi][ni][3] + bs1;
            if (EPI == 1) {
                v0 = 0.5f * v0 * (1.0f + erff(v0 * 0.70710678118654752f));
                v1 = 0.5f * v1 * (1.0f + erff(v1 * 0.70710678118654752f));
                v2 = 0.5f * v2 * (1.0f + erff(v2 * 0.70710678118654752f));
                v3 = 0.5f * v3 * (1.0f + erff(v3 * 0.70710678118654752f));
                *(__nv_bfloat162*)(g_hid + (size_t)row * NN + col) =
                    __floats2bfloat162_rn(v0, v1);
                *(__nv_bfloat162*)(g_hid + (size_t)(row + 8) * NN + col) =
                    __floats2bfloat162_rn(v2, v3);
            } else {
                float2 o0 = *(float2*)(Cx + (size_t)row * NN + col);
                float2 o1 = *(float2*)(Cx + (size_t)(row + 8) * NN + col);
                o0.x += v0; o0.y += v1; o1.x += v2; o1.y += v3;
                *(float2*)(Cx + (size_t)row * NN + col)       = o0;
                *(float2*)(Cx + (size_t)(row + 8) * NN + col) = o1;
            }
        }
    }
}

// ================= launch =================
extern "C" void kernel_launch(void* const* d_in, const int* in_sizes, int n_in,
                              void* d_out, int out_size)
{
    const float* x_in = (const float*)d_in[0];
    const int*   pidx = (const int*)  d_in[1];
    const float* Wq   = (const float*)d_in[2];
    const float* Wk   = (const float*)d_in[3];
    const float* Wv   = (const float*)d_in[4];
    const float* Wo   = (const float*)d_in[5];
    const float* bo   = (const float*)d_in[6];
    const float* lng  = (const float*)d_in[7];
    const float* lnb  = (const float*)d_in[8];
    const float* W1   = (const float*)d_in[9];
    const float* b1   = (const float*)d_in[10];
    const float* W2   = (const float*)d_in[11];
    const float* b2   = (const float*)d_in[12];
    const float* ng   = (const float*)d_in[13];
    const float* nb   = (const float*)d_in[14];
    const int*   hp   = (n_in > 16) ? (const int*)d_in[16] : nullptr;

    float* x = (float*)d_out;

    cudaFuncSetAttribute(k_bgemm<DIMM, MLPD, 1>,
                         cudaFuncAttributeMaxDynamicSharedMemorySize, GSMEM_BYTES);
    cudaFuncSetAttribute(k_bgemm<MLPD, DIMM, 2>,
                         cudaFuncAttributeMaxDynamicSharedMemorySize, GSMEM_BYTES);

    __nv_bfloat16* w1b; cudaGetSymbolAddress((void**)&w1b, g_w1b);
    __nv_bfloat16* w2b; cudaGetSymbolAddress((void**)&w2b, g_w2b);

    cudaMemcpyAsync(x, x_in, (size_t)NTOK * DIMM * sizeof(float),
                    cudaMemcpyDeviceToDevice);
    k_idx<<<1, 32>>>(pidx, hp);

    // pre-convert FFN weights to bf16 (once per call; deterministic)
    const int WN = NLAYER * DIMM * MLPD;   // 1,048,576 each
    k_cvt<<<(WN + 255) / 256, 256>>>(W1, w1b, WN);
    k_cvt<<<(WN + 255) / 256, 256>>>(W2, w2b, WN);

    for (int l = 0; l < NLAYER; l++) {
        const size_t wOff = (size_t)l * DIMM * INNERD;
        const size_t fOff = (size_t)l * DIMM * MLPD;

        // --- attention (folded: no full K/V projections) ---
        k_qu   <<<BATCH, 256>>>(x, Wq + wOff, Wk + wOff);
        k_dots <<<dim3((SEQ + 31) / 32, BATCH), 256>>>(x);
        k_stats<<<BATCH * HEADS, 256>>>();
        k_wsum <<<dim3(BATCH, WSLICE), 256>>>(x);
        k_out  <<<BATCH, 256>>>(x, Wv + wOff, Wo + wOff, bo + (size_t)l * DIMM);

        // --- pre-LN -> g_xnb (bf16) ---
        k_ln<<<NTOK / 8, 256>>>(x, nullptr, lng + (size_t)l * DIMM, lnb + (size_t)l * DIMM);

        // --- FFN on bf16 tensor cores (mma.sync + ldmatrix) ---
        k_bgemm<DIMM, MLPD, 1><<<dim3(MLPD / 128, NTOK / 128), 256, GSMEM_BYTES>>>(
            w1b + fOff, b1 + (size_t)l * MLPD, nullptr);
        k_bgemm<MLPD, DIMM, 2><<<dim3(DIMM / 128, NTOK / 128), 256, GSMEM_BYTES>>>(
            w2b + fOff, b2 + (size_t)l * DIMM, x);
    }

    k_ln<<<NTOK / 8, 256>>>(x, x, ng, nb);
}